// round 9
// baseline (speedup 1.0000x reference)
#include <cuda_runtime.h>
#include <cuda_fp16.h>
#include <cstdint>

#define NN 50000
#define EE 1600000
#define RR 50
#define BB 30
#define HH 16
#define CC 4
#define NH  (NN * HH)
#define NH4 (NN * HH / 4)   // 200000 4-half chunks
#define RCH 25              // relations per k_w1 part

// ---------------- scratch (device globals; no allocation) ----------------
__device__ uint4  g_w1h[(size_t)RR * NN * 2];      // [R,N,H] fp16: 32B/row, 80MB
__device__ float4 g_w2[RR * HH * CC / 4];          // [R,H,C]
__device__ uint4  g_xsumh[NN * 2];                 // layer1 accumulator, fp16
__device__ float4 g_x[NN * HH / 4];                // relu'd hidden (fp32, for k_out)
__device__ uint4  g_xh[NN * 2];                    // relu'd hidden (fp16, for edge2 gather)
__device__ float  g_cnt[NN];                       // in-degree (float)
__device__ float4 g_osum[NN];                      // layer2 accumulator [N,C] fp32

// fp32 v4 reduction
__device__ __forceinline__ void red4(float4* p, float4 v) {
    asm volatile("red.global.add.v4.f32 [%0], {%1, %2, %3, %4};"
                 :: "l"(p), "f"(v.x), "f"(v.y), "f"(v.z), "f"(v.w) : "memory");
}
// fp16x2 v4 reduction: adds 8 packed halves in one atomic op
__device__ __forceinline__ void red4h(uint4* p, uint4 v) {
    asm volatile("red.global.add.noftz.v4.f16x2 [%0], {%1, %2, %3, %4};"
                 :: "l"(p), "r"(v.x), "r"(v.y), "r"(v.z), "r"(v.w) : "memory");
}
__device__ __forceinline__ void fma4(float4& a, float s, float4 w) {
    a.x += s * w.x; a.y += s * w.y; a.z += s * w.z; a.w += s * w.w;
}
__device__ __forceinline__ unsigned int h2bits(__half2 h) { return *(unsigned int*)&h; }
__device__ __forceinline__ __half2 bits2h(unsigned int u) { return *(__half2*)&u; }

// ---------------- K0: zero the accumulators ----------------
__global__ void k_zero() {
    int i = blockIdx.x * blockDim.x + threadIdx.x;
    uint4 zu = make_uint4(0u, 0u, 0u, 0u);
    if (i < NN * 2) g_xsumh[i] = zu;
    if (i < NN) { g_cnt[i] = 0.f; g_osum[i] = make_float4(0.f, 0.f, 0.f, 0.f); }
}

// ---------------- K_w2: w2[r,h,c] = sum_b comp2[r,b] * basis2[b,h,c] ----------------
__global__ void k_w2(const float* __restrict__ comp2, const float* __restrict__ basis2) {
    __shared__ float sc[RR * BB];
    __shared__ float sb[BB * HH * CC];
    for (int i = threadIdx.x; i < RR * BB; i += blockDim.x) sc[i] = comp2[i];
    for (int i = threadIdx.x; i < BB * HH * CC; i += blockDim.x) sb[i] = basis2[i];
    __syncthreads();
    float* w2f = (float*)g_w2;
    for (int i = threadIdx.x; i < RR * HH * CC; i += blockDim.x) {
        int r = i / (HH * CC);
        int hc = i % (HH * CC);
        float acc = 0.f;
        #pragma unroll
        for (int b = 0; b < BB; b++) acc += sc[r * BB + b] * sb[b * HH * CC + hc];
        w2f[i] = acc;
    }
}

// ---------------- K1 (x2): w1[r0..r0+24, n, h] = sum_b comp1[r,b]*basis1[b,n,h] ----------------
// b-outer / r-inner: 25 relations -> 50 half2 accumulators (no spills),
// exactly 1 LDG in flight per iteration (MLP_p1=1).
__global__ void __launch_bounds__(128) k_w1_part(const float4* __restrict__ basis1,
                                                 const float* __restrict__ comp1,
                                                 int r0) {
    __shared__ unsigned int sch[RCH * BB];   // 3 KB: half2(c,c), [r_local][b]
    for (int i = threadIdx.x; i < RCH * BB; i += blockDim.x) {
        float c = comp1[(r0 + i / BB) * BB + (i % BB)];
        sch[i] = h2bits(__floats2half2_rn(c, c));
    }
    __syncthreads();

    int i4 = blockIdx.x * blockDim.x + threadIdx.x;
    if (i4 >= NH4) return;

    __half2 a0[RCH], a1[RCH];
    const __half2 hz = __floats2half2_rn(0.f, 0.f);
    #pragma unroll
    for (int r = 0; r < RCH; r++) { a0[r] = hz; a1[r] = hz; }

    #pragma unroll 1
    for (int b = 0; b < BB; b++) {
        float4 v = basis1[(size_t)b * NH4 + i4];
        __half2 lo = __floats2half2_rn(v.x, v.y);
        __half2 hi = __floats2half2_rn(v.z, v.w);
        const unsigned int* cb = &sch[b];
        #pragma unroll
        for (int r = 0; r < RCH; r++) {
            __half2 cc = bits2h(cb[r * BB]);
            a0[r] = __hfma2(cc, lo, a0[r]);
            a1[r] = __hfma2(cc, hi, a1[r]);
        }
    }

    int n = i4 >> 2;
    int q = i4 & 3;
    uint2* outp = (uint2*)g_w1h;
    #pragma unroll
    for (int r = 0; r < RCH; r++) {
        uint2 o;
        o.x = h2bits(a0[r]);
        o.y = h2bits(a1[r]);
        outp[(((size_t)(r0 + r) * NN + n) << 2) + q] = o;
    }
}

// ---------------- K2: layer-1 edge pass: gather fp16 w1 row (32B), fp16x2 vector RED ----------------
__global__ void k_edge1(const int* __restrict__ ei, const int* __restrict__ et) {
    int e = blockIdx.x * blockDim.x + threadIdx.x;
    if (e >= EE) return;
    int s = ei[e];
    int d = ei[EE + e];
    int t = et[e];
    const uint4* row = g_w1h + ((size_t)t * NN + s) * 2;
    uint4 a = row[0], b = row[1];
    uint4* dst = g_xsumh + d * 2;
    red4h(dst + 0, a);
    red4h(dst + 1, b);
    atomicAdd(&g_cnt[d], 1.0f);
}

// ---------------- K3: x = relu(xsum/max(cnt,1) + root1 + bias1), fp32 + fp16 copies ----------------
__global__ void k_x(const float4* __restrict__ root1, const float4* __restrict__ bias1) {
    int n = blockIdx.x * blockDim.x + threadIdx.x;
    if (n >= NN) return;
    float inv = 1.f / fmaxf(g_cnt[n], 1.f);
    uint4 a = g_xsumh[n * 2];
    uint4 b = g_xsumh[n * 2 + 1];
    unsigned int w[8] = {a.x, a.y, a.z, a.w, b.x, b.y, b.z, b.w};
    unsigned int hx[8];
    #pragma unroll
    for (int j = 0; j < 4; j++) {
        float2 lo = __half22float2(bits2h(w[j * 2]));
        float2 hi = __half22float2(bits2h(w[j * 2 + 1]));
        float4 rv = root1[n * 4 + j];
        float4 bv = bias1[j];
        float4 o;
        o.x = fmaxf(lo.x * inv + rv.x + bv.x, 0.f);
        o.y = fmaxf(lo.y * inv + rv.y + bv.y, 0.f);
        o.z = fmaxf(hi.x * inv + rv.z + bv.z, 0.f);
        o.w = fmaxf(hi.y * inv + rv.w + bv.w, 0.f);
        g_x[n * 4 + j] = o;
        hx[j * 2]     = h2bits(__floats2half2_rn(o.x, o.y));
        hx[j * 2 + 1] = h2bits(__floats2half2_rn(o.z, o.w));
    }
    g_xh[n * 2]     = make_uint4(hx[0], hx[1], hx[2], hx[3]);
    g_xh[n * 2 + 1] = make_uint4(hx[4], hx[5], hx[6], hx[7]);
}

// ---------------- K4: layer-2 edge pass: gather fp16 x (32B), fp32 math, fp32 RED ----------------
__global__ void k_edge2(const int* __restrict__ ei, const int* __restrict__ et) {
    __shared__ float4 sw2[RR * HH];  // 12.8 KB
    for (int i = threadIdx.x; i < RR * HH; i += blockDim.x) sw2[i] = g_w2[i];
    __syncthreads();

    int e = blockIdx.x * blockDim.x + threadIdx.x;
    if (e >= EE) return;
    int s = ei[e];
    int d = ei[EE + e];
    int t = et[e];

    uint4 xa = g_xh[s * 2];
    uint4 xb = g_xh[s * 2 + 1];
    unsigned int xw[8] = {xa.x, xa.y, xa.z, xa.w, xb.x, xb.y, xb.z, xb.w};
    float xf[16];
    #pragma unroll
    for (int j = 0; j < 8; j++) {
        float2 f = __half22float2(bits2h(xw[j]));
        xf[j * 2] = f.x;
        xf[j * 2 + 1] = f.y;
    }

    const float4* w = &sw2[t * HH];
    float4 acc = make_float4(0.f, 0.f, 0.f, 0.f);
    #pragma unroll
    for (int h = 0; h < HH; h++) fma4(acc, xf[h], w[h]);

    red4(&g_osum[d], acc);
}

// ---------------- K5: out = log_softmax(osum/max(cnt,1) + x @ root2 + bias2) ----------------
__global__ void k_out(const float4* __restrict__ root2, const float4* __restrict__ bias2,
                      float4* __restrict__ out) {
    __shared__ float4 sr2[HH];
    __shared__ float4 sb2;
    if (threadIdx.x < HH) sr2[threadIdx.x] = root2[threadIdx.x];
    if (threadIdx.x == 0) sb2 = bias2[0];
    __syncthreads();

    int n = blockIdx.x * blockDim.x + threadIdx.x;
    if (n >= NN) return;

    float inv = 1.f / fmaxf(g_cnt[n], 1.f);
    float4 os = g_osum[n];
    float4 acc;
    acc.x = os.x * inv + sb2.x;
    acc.y = os.y * inv + sb2.y;
    acc.z = os.z * inv + sb2.z;
    acc.w = os.w * inv + sb2.w;

    const float4* xr = g_x + n * 4;
    #pragma unroll
    for (int j = 0; j < 4; j++) {
        float4 xv = xr[j];
        fma4(acc, xv.x, sr2[j * 4 + 0]);
        fma4(acc, xv.y, sr2[j * 4 + 1]);
        fma4(acc, xv.z, sr2[j * 4 + 2]);
        fma4(acc, xv.w, sr2[j * 4 + 3]);
    }

    float m = fmaxf(fmaxf(acc.x, acc.y), fmaxf(acc.z, acc.w));
    float se = expf(acc.x - m) + expf(acc.y - m) + expf(acc.z - m) + expf(acc.w - m);
    float l = m + logf(se);
    float4 o;
    o.x = acc.x - l; o.y = acc.y - l; o.z = acc.z - l; o.w = acc.w - l;
    out[n] = o;
}

// ---------------- launcher ----------------
extern "C" void kernel_launch(void* const* d_in, const int* in_sizes, int n_in,
                              void* d_out, int out_size) {
    const int*    ei        = (const int*)d_in[0];         // edge_index [2,E] int32
    const int*    et        = (const int*)d_in[1];         // edge_type  [E]   int32
    // d_in[2] edge_norm: unused by the reference forward
    const float*  basis1    = (const float*)d_in[3];       // [B,N,H]
    const float*  comp1     = (const float*)d_in[4];       // [R,B]
    const float4* root1     = (const float4*)d_in[5];      // [N,H]
    const float4* bias1     = (const float4*)d_in[6];      // [H]
    const float*  basis2    = (const float*)d_in[7];       // [B,H,C]
    const float*  comp2     = (const float*)d_in[8];       // [R,B]
    const float4* root2     = (const float4*)d_in[9];      // [H,C]
    const float4* bias2     = (const float4*)d_in[10];     // [C]
    float4* out = (float4*)d_out;

    (void)in_sizes; (void)n_in; (void)out_size;

    k_zero   <<<(NN * 2 + 255) / 256, 256>>>();
    k_w2     <<<1, 256>>>(comp2, basis2);
    k_w1_part<<<(NH4 + 127) / 128, 128>>>((const float4*)basis1, comp1, 0);
    k_w1_part<<<(NH4 + 127) / 128, 128>>>((const float4*)basis1, comp1, RCH);
    k_edge1  <<<(EE + 255) / 256, 256>>>(ei, et);
    k_x      <<<(NN + 255) / 256, 256>>>(root1, bias1);
    k_edge2  <<<(EE + 255) / 256, 256>>>(ei, et);
    k_out    <<<(NN + 255) / 256, 256>>>(root2, bias2, out);
}

// round 10
// speedup vs baseline: 1.1310x; 1.1310x over previous
#include <cuda_runtime.h>
#include <cuda_fp16.h>
#include <cstdint>

#define NN 50000
#define EE 1600000
#define RR 50
#define BB 30
#define HH 16
#define CC 4
#define NH  (NN * HH)
#define NH4 (NN * HH / 4)   // 200000 4-half chunks
#define RCH 25              // relations per w1 y-slice

// ---------------- scratch (device globals; no allocation) ----------------
__device__ uint4  g_w1h[(size_t)RR * NN * 2];      // [R,N,H] fp16: 32B/row, 80MB
__device__ float4 g_w2[RR * HH];                   // [R,H,C] fp32 (LDG.128 rows)
__device__ uint4  g_xsumh[NN * 2];                 // layer1 accumulator, fp16
__device__ float4 g_x[NN * HH / 4];                // relu'd hidden (fp32, for k_out)
__device__ uint4  g_xh[NN * 2];                    // relu'd hidden (fp16, edge2 gather)
__device__ float  g_cnt[NN];                       // in-degree (float)
__device__ float4 g_osum[NN];                      // layer2 accumulator [N,C] fp32

// fp32 v4 reduction
__device__ __forceinline__ void red4(float4* p, float4 v) {
    asm volatile("red.global.add.v4.f32 [%0], {%1, %2, %3, %4};"
                 :: "l"(p), "f"(v.x), "f"(v.y), "f"(v.z), "f"(v.w) : "memory");
}
// fp16x2 v4 reduction
__device__ __forceinline__ void red4h(uint4* p, uint4 v) {
    asm volatile("red.global.add.noftz.v4.f16x2 [%0], {%1, %2, %3, %4};"
                 :: "l"(p), "r"(v.x), "r"(v.y), "r"(v.z), "r"(v.w) : "memory");
}
__device__ __forceinline__ void fma4(float4& a, float s, float4 w) {
    a.x += s * w.x; a.y += s * w.y; a.z += s * w.z; a.w += s * w.w;
}
__device__ __forceinline__ unsigned int h2bits(__half2 h) { return *(unsigned int*)&h; }
__device__ __forceinline__ __half2 bits2h(unsigned int u) { return *(__half2*)&u; }

// ---------------- K1: w1 slice + accumulator zeroing (launch 1) ----------------
// grid (1563, 2): y selects relations [y*25, y*25+25). y==0 blocks also zero
// the scatter accumulators (consumed only by later kernels).
__global__ void __launch_bounds__(128) k_w1(const float4* __restrict__ basis1,
                                            const float* __restrict__ comp1) {
    int r0 = blockIdx.y * RCH;
    __shared__ unsigned int sch[RCH * BB];   // 3 KB: half2(c,c), [r_local][b]
    for (int i = threadIdx.x; i < RCH * BB; i += blockDim.x) {
        float c = comp1[(r0 + i / BB) * BB + (i % BB)];
        sch[i] = h2bits(__floats2half2_rn(c, c));
    }

    int i4 = blockIdx.x * blockDim.x + threadIdx.x;

    // fold in accumulator zeroing (disjoint arrays; edge kernels run later)
    if (blockIdx.y == 0 && i4 < NN * 2 + NN + NN) {
        if (i4 < NN * 2) {
            g_xsumh[i4] = make_uint4(0u, 0u, 0u, 0u);
        } else if (i4 < NN * 2 + NN) {
            g_osum[i4 - NN * 2] = make_float4(0.f, 0.f, 0.f, 0.f);
        } else {
            g_cnt[i4 - NN * 3] = 0.f;
        }
    }
    __syncthreads();

    if (i4 >= NH4) return;

    __half2 a0[RCH], a1[RCH];
    const __half2 hz = __floats2half2_rn(0.f, 0.f);
    #pragma unroll
    for (int r = 0; r < RCH; r++) { a0[r] = hz; a1[r] = hz; }

    #pragma unroll 1
    for (int b = 0; b < BB; b++) {
        float4 v = basis1[(size_t)b * NH4 + i4];
        __half2 lo = __floats2half2_rn(v.x, v.y);
        __half2 hi = __floats2half2_rn(v.z, v.w);
        const unsigned int* cb = &sch[b];
        #pragma unroll
        for (int r = 0; r < RCH; r++) {
            __half2 cc = bits2h(cb[r * BB]);
            a0[r] = __hfma2(cc, lo, a0[r]);
            a1[r] = __hfma2(cc, hi, a1[r]);
        }
    }

    int n = i4 >> 2;
    int q = i4 & 3;
    uint2* outp = (uint2*)g_w1h;
    #pragma unroll
    for (int r = 0; r < RCH; r++) {
        uint2 o;
        o.x = h2bits(a0[r]);
        o.y = h2bits(a1[r]);
        outp[(((size_t)(r0 + r) * NN + n) << 2) + q] = o;
    }
}

// ---------------- K2: layer-1 edge pass (launch 2) ----------------
__global__ void k_edge1(const int* __restrict__ ei, const int* __restrict__ et) {
    int e = blockIdx.x * blockDim.x + threadIdx.x;
    if (e >= EE) return;
    int s = ei[e];
    int d = ei[EE + e];
    int t = et[e];
    const uint4* row = g_w1h + ((size_t)t * NN + s) * 2;
    uint4 a = row[0], b = row[1];
    uint4* dst = g_xsumh + d * 2;
    red4h(dst + 0, a);
    red4h(dst + 1, b);
    atomicAdd(&g_cnt[d], 1.0f);
}

// ---------------- K3: x = relu(mean + root1 + bias1), plus w2 build (launch 3) ----------------
// Blocks [0,195]: k_x. Block 196: w2[r,h,c] = sum_b comp2[r,b]*basis2[b,h,c].
__global__ void k_x_w2(const float4* __restrict__ root1, const float4* __restrict__ bias1,
                       const float* __restrict__ comp2, const float* __restrict__ basis2) {
    if (blockIdx.x == (NN + 255) / 256) {
        __shared__ float sc[RR * BB];
        __shared__ float sb[BB * HH * CC];
        for (int i = threadIdx.x; i < RR * BB; i += blockDim.x) sc[i] = comp2[i];
        for (int i = threadIdx.x; i < BB * HH * CC; i += blockDim.x) sb[i] = basis2[i];
        __syncthreads();
        float* w2f = (float*)g_w2;
        for (int i = threadIdx.x; i < RR * HH * CC; i += blockDim.x) {
            int r = i / (HH * CC);
            int hc = i % (HH * CC);
            float acc = 0.f;
            #pragma unroll
            for (int b = 0; b < BB; b++) acc += sc[r * BB + b] * sb[b * HH * CC + hc];
            w2f[i] = acc;
        }
        return;
    }

    int n = blockIdx.x * blockDim.x + threadIdx.x;
    if (n >= NN) return;
    float inv = 1.f / fmaxf(g_cnt[n], 1.f);
    uint4 a = g_xsumh[n * 2];
    uint4 b = g_xsumh[n * 2 + 1];
    unsigned int w[8] = {a.x, a.y, a.z, a.w, b.x, b.y, b.z, b.w};
    unsigned int hx[8];
    #pragma unroll
    for (int j = 0; j < 4; j++) {
        float2 lo = __half22float2(bits2h(w[j * 2]));
        float2 hi = __half22float2(bits2h(w[j * 2 + 1]));
        float4 rv = root1[n * 4 + j];
        float4 bv = bias1[j];
        float4 o;
        o.x = fmaxf(lo.x * inv + rv.x + bv.x, 0.f);
        o.y = fmaxf(lo.y * inv + rv.y + bv.y, 0.f);
        o.z = fmaxf(hi.x * inv + rv.z + bv.z, 0.f);
        o.w = fmaxf(hi.y * inv + rv.w + bv.w, 0.f);
        g_x[n * 4 + j] = o;
        hx[j * 2]     = h2bits(__floats2half2_rn(o.x, o.y));
        hx[j * 2 + 1] = h2bits(__floats2half2_rn(o.z, o.w));
    }
    g_xh[n * 2]     = make_uint4(hx[0], hx[1], hx[2], hx[3]);
    g_xh[n * 2 + 1] = make_uint4(hx[4], hx[5], hx[6], hx[7]);
}

// ---------------- K4: layer-2 edge pass (launch 4, profiled slot) ----------------
// No smem: w2 rows read via divergent LDG.128 from the L1-resident 12.8KB
// table (sector-based, conflict-free), x gathered fp16 (L2-resident).
__global__ void k_edge2(const int* __restrict__ ei, const int* __restrict__ et) {
    int e = blockIdx.x * blockDim.x + threadIdx.x;
    if (e >= EE) return;
    int s = ei[e];
    int d = ei[EE + e];
    int t = et[e];

    uint4 xa = g_xh[s * 2];
    uint4 xb = g_xh[s * 2 + 1];
    unsigned int xw[8] = {xa.x, xa.y, xa.z, xa.w, xb.x, xb.y, xb.z, xb.w};
    float xf[16];
    #pragma unroll
    for (int j = 0; j < 8; j++) {
        float2 f = __half22float2(bits2h(xw[j]));
        xf[j * 2] = f.x;
        xf[j * 2 + 1] = f.y;
    }

    const float4* w = g_w2 + t * HH;
    float4 acc = make_float4(0.f, 0.f, 0.f, 0.f);
    #pragma unroll
    for (int h = 0; h < HH; h++) fma4(acc, xf[h], __ldg(w + h));

    red4(&g_osum[d], acc);
}

// ---------------- K5: out = log_softmax(osum/max(cnt,1) + x @ root2 + bias2) ----------------
__global__ void k_out(const float4* __restrict__ root2, const float4* __restrict__ bias2,
                      float4* __restrict__ out) {
    __shared__ float4 sr2[HH];
    __shared__ float4 sb2;
    if (threadIdx.x < HH) sr2[threadIdx.x] = root2[threadIdx.x];
    if (threadIdx.x == 0) sb2 = bias2[0];
    __syncthreads();

    int n = blockIdx.x * blockDim.x + threadIdx.x;
    if (n >= NN) return;

    float inv = 1.f / fmaxf(g_cnt[n], 1.f);
    float4 os = g_osum[n];
    float4 acc;
    acc.x = os.x * inv + sb2.x;
    acc.y = os.y * inv + sb2.y;
    acc.z = os.z * inv + sb2.z;
    acc.w = os.w * inv + sb2.w;

    const float4* xr = g_x + n * 4;
    #pragma unroll
    for (int j = 0; j < 4; j++) {
        float4 xv = xr[j];
        fma4(acc, xv.x, sr2[j * 4 + 0]);
        fma4(acc, xv.y, sr2[j * 4 + 1]);
        fma4(acc, xv.z, sr2[j * 4 + 2]);
        fma4(acc, xv.w, sr2[j * 4 + 3]);
    }

    float m = fmaxf(fmaxf(acc.x, acc.y), fmaxf(acc.z, acc.w));
    float se = expf(acc.x - m) + expf(acc.y - m) + expf(acc.z - m) + expf(acc.w - m);
    float l = m + logf(se);
    float4 o;
    o.x = acc.x - l; o.y = acc.y - l; o.z = acc.z - l; o.w = acc.w - l;
    out[n] = o;
}

// ---------------- launcher (5 graph nodes) ----------------
extern "C" void kernel_launch(void* const* d_in, const int* in_sizes, int n_in,
                              void* d_out, int out_size) {
    const int*    ei        = (const int*)d_in[0];         // edge_index [2,E] int32
    const int*    et        = (const int*)d_in[1];         // edge_type  [E]   int32
    // d_in[2] edge_norm: unused by the reference forward
    const float*  basis1    = (const float*)d_in[3];       // [B,N,H]
    const float*  comp1     = (const float*)d_in[4];       // [R,B]
    const float4* root1     = (const float4*)d_in[5];      // [N,H]
    const float4* bias1     = (const float4*)d_in[6];      // [H]
    const float*  basis2    = (const float*)d_in[7];       // [B,H,C]
    const float*  comp2     = (const float*)d_in[8];       // [R,B]
    const float4* root2     = (const float4*)d_in[9];      // [H,C]
    const float4* bias2     = (const float4*)d_in[10];     // [C]
    float4* out = (float4*)d_out;

    (void)in_sizes; (void)n_in; (void)out_size;

    dim3 gw1((NH4 + 127) / 128, 2);
    k_w1   <<<gw1, 128>>>((const float4*)basis1, comp1);
    k_edge1<<<(EE + 255) / 256, 256>>>(ei, et);
    k_x_w2 <<<(NN + 255) / 256 + 1, 256>>>(root1, bias1, comp2, basis2);
    k_edge2<<<(EE + 255) / 256, 256>>>(ei, et);
    k_out  <<<(NN + 255) / 256, 256>>>(root2, bias2, out);
}

// round 11
// speedup vs baseline: 1.4513x; 1.2832x over previous
#include <cuda_runtime.h>
#include <cuda_fp16.h>
#include <cstdint>

#define NN 50000
#define EE 1600000
#define RR 50
#define BB 30
#define HH 16
#define CC 4
#define NH  (NN * HH)
#define NH4 (NN * HH / 4)   // 200000 4-half chunks
#define RCH 25              // relations per w1 y-slice

// ---------------- scratch (device globals; no allocation) ----------------
__device__ uint4  g_w1h[(size_t)RR * NN * 2];      // [R,N,H] fp16: 32B/row, 80MB
__device__ float4 g_w2[RR * HH];                   // [R,H,C] fp32
__device__ uint4  g_xsumh[NN * 2];                 // layer1 accumulator, fp16
__device__ float4 g_x[NN * HH / 4];                // relu'd hidden (fp32, for k_out)
__device__ uint4  g_xh[NN * 2];                    // relu'd hidden (fp16, edge2 gather)
__device__ float  g_cnt[NN];                       // in-degree (float)
__device__ float4 g_osum[NN];                      // layer2 accumulator [N,C] fp32

// fp32 v4 reduction
__device__ __forceinline__ void red4(float4* p, float4 v) {
    asm volatile("red.global.add.v4.f32 [%0], {%1, %2, %3, %4};"
                 :: "l"(p), "f"(v.x), "f"(v.y), "f"(v.z), "f"(v.w) : "memory");
}
// fp16x2 v4 reduction
__device__ __forceinline__ void red4h(uint4* p, uint4 v) {
    asm volatile("red.global.add.noftz.v4.f16x2 [%0], {%1, %2, %3, %4};"
                 :: "l"(p), "r"(v.x), "r"(v.y), "r"(v.z), "r"(v.w) : "memory");
}
__device__ __forceinline__ void fma4(float4& a, float s, float4 w) {
    a.x += s * w.x; a.y += s * w.y; a.z += s * w.z; a.w += s * w.w;
}
__device__ __forceinline__ unsigned int h2bits(__half2 h) { return *(unsigned int*)&h; }
__device__ __forceinline__ __half2 bits2h(unsigned int u) { return *(__half2*)&u; }

// ---------------- K1: w1 slice + accumulator zeroing (launch 1) ----------------
__global__ void __launch_bounds__(128) k_w1(const float4* __restrict__ basis1,
                                            const float* __restrict__ comp1) {
    int r0 = blockIdx.y * RCH;
    __shared__ unsigned int sch[RCH * BB];   // 3 KB: half2(c,c), [r_local][b]
    for (int i = threadIdx.x; i < RCH * BB; i += blockDim.x) {
        float c = comp1[(r0 + i / BB) * BB + (i % BB)];
        sch[i] = h2bits(__floats2half2_rn(c, c));
    }

    int i4 = blockIdx.x * blockDim.x + threadIdx.x;

    // fold in accumulator zeroing (disjoint arrays; edge kernels run later)
    if (blockIdx.y == 0 && i4 < NN * 2 + NN + NN) {
        if (i4 < NN * 2) {
            g_xsumh[i4] = make_uint4(0u, 0u, 0u, 0u);
        } else if (i4 < NN * 2 + NN) {
            g_osum[i4 - NN * 2] = make_float4(0.f, 0.f, 0.f, 0.f);
        } else {
            g_cnt[i4 - NN * 3] = 0.f;
        }
    }
    __syncthreads();

    if (i4 >= NH4) return;

    __half2 a0[RCH], a1[RCH];
    const __half2 hz = __floats2half2_rn(0.f, 0.f);
    #pragma unroll
    for (int r = 0; r < RCH; r++) { a0[r] = hz; a1[r] = hz; }

    #pragma unroll 1
    for (int b = 0; b < BB; b++) {
        float4 v = basis1[(size_t)b * NH4 + i4];
        __half2 lo = __floats2half2_rn(v.x, v.y);
        __half2 hi = __floats2half2_rn(v.z, v.w);
        const unsigned int* cb = &sch[b];
        #pragma unroll
        for (int r = 0; r < RCH; r++) {
            __half2 cc = bits2h(cb[r * BB]);
            a0[r] = __hfma2(cc, lo, a0[r]);
            a1[r] = __hfma2(cc, hi, a1[r]);
        }
    }

    int n = i4 >> 2;
    int q = i4 & 3;
    uint2* outp = (uint2*)g_w1h;
    #pragma unroll
    for (int r = 0; r < RCH; r++) {
        uint2 o;
        o.x = h2bits(a0[r]);
        o.y = h2bits(a1[r]);
        outp[(((size_t)(r0 + r) * NN + n) << 2) + q] = o;
    }
}

// ---------------- K2: layer-1 edge pass (launch 2) ----------------
__global__ void k_edge1(const int* __restrict__ ei, const int* __restrict__ et) {
    int e = blockIdx.x * blockDim.x + threadIdx.x;
    if (e >= EE) return;
    int s = ei[e];
    int d = ei[EE + e];
    int t = et[e];
    const uint4* row = g_w1h + ((size_t)t * NN + s) * 2;
    uint4 a = row[0], b = row[1];
    uint4* dst = g_xsumh + d * 2;
    red4h(dst + 0, a);
    red4h(dst + 1, b);
    atomicAdd(&g_cnt[d], 1.0f);
}

// ---------------- K3: x = relu(mean + root1 + bias1), plus w2 build (launch 3) ----------------
__global__ void k_x_w2(const float4* __restrict__ root1, const float4* __restrict__ bias1,
                       const float* __restrict__ comp2, const float* __restrict__ basis2) {
    if (blockIdx.x == (NN + 255) / 256) {
        __shared__ float sc[RR * BB];
        __shared__ float sb[BB * HH * CC];
        for (int i = threadIdx.x; i < RR * BB; i += blockDim.x) sc[i] = comp2[i];
        for (int i = threadIdx.x; i < BB * HH * CC; i += blockDim.x) sb[i] = basis2[i];
        __syncthreads();
        float* w2f = (float*)g_w2;
        for (int i = threadIdx.x; i < RR * HH * CC; i += blockDim.x) {
            int r = i / (HH * CC);
            int hc = i % (HH * CC);
            float acc = 0.f;
            #pragma unroll
            for (int b = 0; b < BB; b++) acc += sc[r * BB + b] * sb[b * HH * CC + hc];
            w2f[i] = acc;
        }
        return;
    }

    int n = blockIdx.x * blockDim.x + threadIdx.x;
    if (n >= NN) return;
    float inv = 1.f / fmaxf(g_cnt[n], 1.f);
    uint4 a = g_xsumh[n * 2];
    uint4 b = g_xsumh[n * 2 + 1];
    unsigned int w[8] = {a.x, a.y, a.z, a.w, b.x, b.y, b.z, b.w};
    unsigned int hx[8];
    #pragma unroll
    for (int j = 0; j < 4; j++) {
        float2 lo = __half22float2(bits2h(w[j * 2]));
        float2 hi = __half22float2(bits2h(w[j * 2 + 1]));
        float4 rv = root1[n * 4 + j];
        float4 bv = bias1[j];
        float4 o;
        o.x = fmaxf(lo.x * inv + rv.x + bv.x, 0.f);
        o.y = fmaxf(lo.y * inv + rv.y + bv.y, 0.f);
        o.z = fmaxf(hi.x * inv + rv.z + bv.z, 0.f);
        o.w = fmaxf(hi.y * inv + rv.w + bv.w, 0.f);
        g_x[n * 4 + j] = o;
        hx[j * 2]     = h2bits(__floats2half2_rn(o.x, o.y));
        hx[j * 2 + 1] = h2bits(__floats2half2_rn(o.z, o.w));
    }
    g_xh[n * 2]     = make_uint4(hx[0], hx[1], hx[2], hx[3]);
    g_xh[n * 2 + 1] = make_uint4(hx[4], hx[5], hx[6], hx[7]);
}

// ---------------- K4: layer-2 edge pass (launch 4, profiled slot) ----------------
// w2 staged in smem fp16 TRANSPOSED [h][t] (half4 entries, stride 64):
// per-h divergent access footprint = 8B/lane over 50 entries -> ~3-way bank
// conflicts instead of 32-way / 25-line L1 divergence.
__global__ void k_edge2(const int* __restrict__ ei, const int* __restrict__ et) {
    __shared__ unsigned long long sw2h[HH * 64];  // 8 KB, [h*64 + t]
    for (int i = threadIdx.x; i < RR * HH; i += blockDim.x) {
        int r = i / HH, h = i % HH;
        float4 w = g_w2[r * HH + h];
        uint2 p;
        p.x = h2bits(__floats2half2_rn(w.x, w.y));
        p.y = h2bits(__floats2half2_rn(w.z, w.w));
        sw2h[h * 64 + r] = *(unsigned long long*)&p;
    }
    __syncthreads();

    int e = blockIdx.x * blockDim.x + threadIdx.x;
    if (e >= EE) return;
    int s = ei[e];
    int d = ei[EE + e];
    int t = et[e];

    uint4 xa = g_xh[s * 2];
    uint4 xb = g_xh[s * 2 + 1];
    unsigned int xw[8] = {xa.x, xa.y, xa.z, xa.w, xb.x, xb.y, xb.z, xb.w};
    float xf[16];
    #pragma unroll
    for (int j = 0; j < 8; j++) {
        float2 f = __half22float2(bits2h(xw[j]));
        xf[j * 2] = f.x;
        xf[j * 2 + 1] = f.y;
    }

    float4 acc = make_float4(0.f, 0.f, 0.f, 0.f);
    #pragma unroll
    for (int h = 0; h < HH; h++) {
        unsigned long long wp = sw2h[h * 64 + t];
        uint2 p = *(uint2*)&wp;
        float2 wlo = __half22float2(bits2h(p.x));
        float2 whi = __half22float2(bits2h(p.y));
        fma4(acc, xf[h], make_float4(wlo.x, wlo.y, whi.x, whi.y));
    }

    red4(&g_osum[d], acc);
}

// ---------------- K5: out = log_softmax(osum/max(cnt,1) + x @ root2 + bias2) ----------------
__global__ void k_out(const float4* __restrict__ root2, const float4* __restrict__ bias2,
                      float4* __restrict__ out) {
    __shared__ float4 sr2[HH];
    __shared__ float4 sb2;
    if (threadIdx.x < HH) sr2[threadIdx.x] = root2[threadIdx.x];
    if (threadIdx.x == 0) sb2 = bias2[0];
    __syncthreads();

    int n = blockIdx.x * blockDim.x + threadIdx.x;
    if (n >= NN) return;

    float inv = 1.f / fmaxf(g_cnt[n], 1.f);
    float4 os = g_osum[n];
    float4 acc;
    acc.x = os.x * inv + sb2.x;
    acc.y = os.y * inv + sb2.y;
    acc.z = os.z * inv + sb2.z;
    acc.w = os.w * inv + sb2.w;

    const float4* xr = g_x + n * 4;
    #pragma unroll
    for (int j = 0; j < 4; j++) {
        float4 xv = xr[j];
        fma4(acc, xv.x, sr2[j * 4 + 0]);
        fma4(acc, xv.y, sr2[j * 4 + 1]);
        fma4(acc, xv.z, sr2[j * 4 + 2]);
        fma4(acc, xv.w, sr2[j * 4 + 3]);
    }

    float m = fmaxf(fmaxf(acc.x, acc.y), fmaxf(acc.z, acc.w));
    float se = expf(acc.x - m) + expf(acc.y - m) + expf(acc.z - m) + expf(acc.w - m);
    float l = m + logf(se);
    float4 o;
    o.x = acc.x - l; o.y = acc.y - l; o.z = acc.z - l; o.w = acc.w - l;
    out[n] = o;
}

// ---------------- launcher (5 graph nodes) ----------------
extern "C" void kernel_launch(void* const* d_in, const int* in_sizes, int n_in,
                              void* d_out, int out_size) {
    const int*    ei        = (const int*)d_in[0];         // edge_index [2,E] int32
    const int*    et        = (const int*)d_in[1];         // edge_type  [E]   int32
    // d_in[2] edge_norm: unused by the reference forward
    const float*  basis1    = (const float*)d_in[3];       // [B,N,H]
    const float*  comp1     = (const float*)d_in[4];       // [R,B]
    const float4* root1     = (const float4*)d_in[5];      // [N,H]
    const float4* bias1     = (const float4*)d_in[6];      // [H]
    const float*  basis2    = (const float*)d_in[7];       // [B,H,C]
    const float*  comp2     = (const float*)d_in[8];       // [R,B]
    const float4* root2     = (const float4*)d_in[9];      // [H,C]
    const float4* bias2     = (const float4*)d_in[10];     // [C]
    float4* out = (float4*)d_out;

    (void)in_sizes; (void)n_in; (void)out_size;

    dim3 gw1((NH4 + 127) / 128, 2);
    k_w1   <<<gw1, 128>>>((const float4*)basis1, comp1);
    k_edge1<<<(EE + 255) / 256, 256>>>(ei, et);
    k_x_w2 <<<(NN + 255) / 256 + 1, 256>>>(root1, bias1, comp2, basis2);
    k_edge2<<<(EE + 255) / 256, 256>>>(ei, et);
    k_out  <<<(NN + 255) / 256, 256>>>(root2, bias2, out);
}

// round 12
// speedup vs baseline: 1.5210x; 1.0480x over previous
#include <cuda_runtime.h>
#include <cuda_fp16.h>
#include <cstdint>

#define NN 50000
#define EE 1600000
#define RR 50
#define BB 30
#define HH 16
#define CC 4
#define NH  (NN * HH)
#define NH4 (NN * HH / 4)   // 200000 4-half chunks
#define RCH 25              // relations per w1 y-slice
#define RPAD 28             // padded r-stride for LDS.128 coef loads

// ---------------- scratch (device globals; no allocation) ----------------
__device__ uint4  g_w1h[(size_t)RR * NN * 2];      // [R,N,H] fp16: 32B/row, 80MB
__device__ float4 g_w2[RR * HH];                   // [R,H,C] fp32
__device__ uint4  g_xsumh[NN * 2];                 // layer1 accumulator, fp16
__device__ float4 g_x[NN * HH / 4];                // relu'd hidden (fp32, for k_out)
__device__ uint4  g_xh[NN * 2];                    // relu'd hidden (fp16, edge2 gather)
__device__ float  g_cnt[NN];                       // in-degree (float)
__device__ float4 g_osum[NN];                      // layer2 accumulator [N,C] fp32

// fp32 v4 reduction
__device__ __forceinline__ void red4(float4* p, float4 v) {
    asm volatile("red.global.add.v4.f32 [%0], {%1, %2, %3, %4};"
                 :: "l"(p), "f"(v.x), "f"(v.y), "f"(v.z), "f"(v.w) : "memory");
}
// fp16x2 v4 reduction
__device__ __forceinline__ void red4h(uint4* p, uint4 v) {
    asm volatile("red.global.add.noftz.v4.f16x2 [%0], {%1, %2, %3, %4};"
                 :: "l"(p), "r"(v.x), "r"(v.y), "r"(v.z), "r"(v.w) : "memory");
}
__device__ __forceinline__ void fma4(float4& a, float s, float4 w) {
    a.x += s * w.x; a.y += s * w.y; a.z += s * w.z; a.w += s * w.w;
}
__device__ __forceinline__ unsigned int h2bits(__half2 h) { return *(unsigned int*)&h; }
__device__ __forceinline__ __half2 bits2h(unsigned int u) { return *(__half2*)&u; }

// ---------------- K1: w1 slice + accumulator zeroing (launch 1) ----------------
// grid (1563, 2). Inner loop: prefetched LDG (2 in flight), LDS.128 coef
// vectors (4 half2 coefs per load), HFMA2 accumulation.
__global__ void __launch_bounds__(128) k_w1(const float4* __restrict__ basis1,
                                            const float* __restrict__ comp1) {
    int r0 = blockIdx.y * RCH;
    __shared__ __align__(16) unsigned int schv[BB * RPAD];  // [b][r] half2(c,c)
    for (int i = threadIdx.x; i < BB * RPAD; i += blockDim.x) {
        int b = i / RPAD, r = i - b * RPAD;
        float c = (r < RCH) ? comp1[(r0 + r) * BB + b] : 0.f;
        schv[i] = h2bits(__floats2half2_rn(c, c));
    }

    int i4 = blockIdx.x * blockDim.x + threadIdx.x;

    // fold in accumulator zeroing (disjoint arrays; edge kernels run later)
    if (blockIdx.y == 0 && i4 < NN * 2 + NN + NN) {
        if (i4 < NN * 2) {
            g_xsumh[i4] = make_uint4(0u, 0u, 0u, 0u);
        } else if (i4 < NN * 2 + NN) {
            g_osum[i4 - NN * 2] = make_float4(0.f, 0.f, 0.f, 0.f);
        } else {
            g_cnt[i4 - NN * 3] = 0.f;
        }
    }
    __syncthreads();

    if (i4 >= NH4) return;

    __half2 a0[RCH], a1[RCH];
    const __half2 hz = __floats2half2_rn(0.f, 0.f);
    #pragma unroll
    for (int r = 0; r < RCH; r++) { a0[r] = hz; a1[r] = hz; }

    float4 v = basis1[i4];   // b = 0
    #pragma unroll 1
    for (int b = 0; b < BB; b++) {
        float4 vn = make_float4(0.f, 0.f, 0.f, 0.f);
        if (b + 1 < BB) vn = basis1[(size_t)(b + 1) * NH4 + i4];  // prefetch (MLP=2)

        __half2 lo = __floats2half2_rn(v.x, v.y);
        __half2 hi = __floats2half2_rn(v.z, v.w);
        const unsigned int* cb = &schv[b * RPAD];

        #pragma unroll
        for (int rg = 0; rg < 6; rg++) {                 // r = 0..23, 4 at a time
            uint4 c4 = *(const uint4*)(cb + rg * 4);
            int r = rg * 4;
            a0[r+0] = __hfma2(bits2h(c4.x), lo, a0[r+0]);
            a1[r+0] = __hfma2(bits2h(c4.x), hi, a1[r+0]);
            a0[r+1] = __hfma2(bits2h(c4.y), lo, a0[r+1]);
            a1[r+1] = __hfma2(bits2h(c4.y), hi, a1[r+1]);
            a0[r+2] = __hfma2(bits2h(c4.z), lo, a0[r+2]);
            a1[r+2] = __hfma2(bits2h(c4.z), hi, a1[r+2]);
            a0[r+3] = __hfma2(bits2h(c4.w), lo, a0[r+3]);
            a1[r+3] = __hfma2(bits2h(c4.w), hi, a1[r+3]);
        }
        {   // r = 24
            __half2 cc = bits2h(cb[24]);
            a0[24] = __hfma2(cc, lo, a0[24]);
            a1[24] = __hfma2(cc, hi, a1[24]);
        }
        v = vn;
    }

    int n = i4 >> 2;
    int q = i4 & 3;
    uint2* outp = (uint2*)g_w1h;
    #pragma unroll
    for (int r = 0; r < RCH; r++) {
        uint2 o;
        o.x = h2bits(a0[r]);
        o.y = h2bits(a1[r]);
        outp[(((size_t)(r0 + r) * NN + n) << 2) + q] = o;
    }
}

// ---------------- K2: layer-1 edge pass (launch 2) ----------------
__global__ void k_edge1(const int* __restrict__ ei, const int* __restrict__ et) {
    int e = blockIdx.x * blockDim.x + threadIdx.x;
    if (e >= EE) return;
    int s = ei[e];
    int d = ei[EE + e];
    int t = et[e];
    const uint4* row = g_w1h + ((size_t)t * NN + s) * 2;
    uint4 a = row[0], b = row[1];
    uint4* dst = g_xsumh + d * 2;
    red4h(dst + 0, a);
    red4h(dst + 1, b);
    atomicAdd(&g_cnt[d], 1.0f);
}

// ---------------- K3: x = relu(mean + root1 + bias1), plus w2 build (launch 3) ----------------
__global__ void k_x_w2(const float4* __restrict__ root1, const float4* __restrict__ bias1,
                       const float* __restrict__ comp2, const float* __restrict__ basis2) {
    if (blockIdx.x == (NN + 255) / 256) {
        __shared__ float sc[RR * BB];
        __shared__ float sb[BB * HH * CC];
        for (int i = threadIdx.x; i < RR * BB; i += blockDim.x) sc[i] = comp2[i];
        for (int i = threadIdx.x; i < BB * HH * CC; i += blockDim.x) sb[i] = basis2[i];
        __syncthreads();
        float* w2f = (float*)g_w2;
        for (int i = threadIdx.x; i < RR * HH * CC; i += blockDim.x) {
            int r = i / (HH * CC);
            int hc = i % (HH * CC);
            float acc = 0.f;
            #pragma unroll
            for (int b = 0; b < BB; b++) acc += sc[r * BB + b] * sb[b * HH * CC + hc];
            w2f[i] = acc;
        }
        return;
    }

    int n = blockIdx.x * blockDim.x + threadIdx.x;
    if (n >= NN) return;
    float inv = 1.f / fmaxf(g_cnt[n], 1.f);
    uint4 a = g_xsumh[n * 2];
    uint4 b = g_xsumh[n * 2 + 1];
    unsigned int w[8] = {a.x, a.y, a.z, a.w, b.x, b.y, b.z, b.w};
    unsigned int hx[8];
    #pragma unroll
    for (int j = 0; j < 4; j++) {
        float2 lo = __half22float2(bits2h(w[j * 2]));
        float2 hi = __half22float2(bits2h(w[j * 2 + 1]));
        float4 rv = root1[n * 4 + j];
        float4 bv = bias1[j];
        float4 o;
        o.x = fmaxf(lo.x * inv + rv.x + bv.x, 0.f);
        o.y = fmaxf(lo.y * inv + rv.y + bv.y, 0.f);
        o.z = fmaxf(hi.x * inv + rv.z + bv.z, 0.f);
        o.w = fmaxf(hi.y * inv + rv.w + bv.w, 0.f);
        g_x[n * 4 + j] = o;
        hx[j * 2]     = h2bits(__floats2half2_rn(o.x, o.y));
        hx[j * 2 + 1] = h2bits(__floats2half2_rn(o.z, o.w));
    }
    g_xh[n * 2]     = make_uint4(hx[0], hx[1], hx[2], hx[3]);
    g_xh[n * 2 + 1] = make_uint4(hx[4], hx[5], hx[6], hx[7]);
}

// ---------------- K4: layer-2 edge pass (launch 4, profiled slot) ----------------
__global__ void k_edge2(const int* __restrict__ ei, const int* __restrict__ et) {
    __shared__ unsigned long long sw2h[HH * 64];  // 8 KB, [h*64 + t]
    for (int i = threadIdx.x; i < RR * HH; i += blockDim.x) {
        int r = i / HH, h = i % HH;
        float4 w = g_w2[r * HH + h];
        uint2 p;
        p.x = h2bits(__floats2half2_rn(w.x, w.y));
        p.y = h2bits(__floats2half2_rn(w.z, w.w));
        sw2h[h * 64 + r] = *(unsigned long long*)&p;
    }
    __syncthreads();

    int e = blockIdx.x * blockDim.x + threadIdx.x;
    if (e >= EE) return;
    int s = ei[e];
    int d = ei[EE + e];
    int t = et[e];

    uint4 xa = g_xh[s * 2];
    uint4 xb = g_xh[s * 2 + 1];
    unsigned int xw[8] = {xa.x, xa.y, xa.z, xa.w, xb.x, xb.y, xb.z, xb.w};
    float xf[16];
    #pragma unroll
    for (int j = 0; j < 8; j++) {
        float2 f = __half22float2(bits2h(xw[j]));
        xf[j * 2] = f.x;
        xf[j * 2 + 1] = f.y;
    }

    float4 acc = make_float4(0.f, 0.f, 0.f, 0.f);
    #pragma unroll
    for (int h = 0; h < HH; h++) {
        unsigned long long wp = sw2h[h * 64 + t];
        uint2 p = *(uint2*)&wp;
        float2 wlo = __half22float2(bits2h(p.x));
        float2 whi = __half22float2(bits2h(p.y));
        fma4(acc, xf[h], make_float4(wlo.x, wlo.y, whi.x, whi.y));
    }

    red4(&g_osum[d], acc);
}

// ---------------- K5: out = log_softmax(osum/max(cnt,1) + x @ root2 + bias2) ----------------
__global__ void k_out(const float4* __restrict__ root2, const float4* __restrict__ bias2,
                      float4* __restrict__ out) {
    __shared__ float4 sr2[HH];
    __shared__ float4 sb2;
    if (threadIdx.x < HH) sr2[threadIdx.x] = root2[threadIdx.x];
    if (threadIdx.x == 0) sb2 = bias2[0];
    __syncthreads();

    int n = blockIdx.x * blockDim.x + threadIdx.x;
    if (n >= NN) return;

    float inv = 1.f / fmaxf(g_cnt[n], 1.f);
    float4 os = g_osum[n];
    float4 acc;
    acc.x = os.x * inv + sb2.x;
    acc.y = os.y * inv + sb2.y;
    acc.z = os.z * inv + sb2.z;
    acc.w = os.w * inv + sb2.w;

    const float4* xr = g_x + n * 4;
    #pragma unroll
    for (int j = 0; j < 4; j++) {
        float4 xv = xr[j];
        fma4(acc, xv.x, sr2[j * 4 + 0]);
        fma4(acc, xv.y, sr2[j * 4 + 1]);
        fma4(acc, xv.z, sr2[j * 4 + 2]);
        fma4(acc, xv.w, sr2[j * 4 + 3]);
    }

    float m = fmaxf(fmaxf(acc.x, acc.y), fmaxf(acc.z, acc.w));
    float se = expf(acc.x - m) + expf(acc.y - m) + expf(acc.z - m) + expf(acc.w - m);
    float l = m + logf(se);
    float4 o;
    o.x = acc.x - l; o.y = acc.y - l; o.z = acc.z - l; o.w = acc.w - l;
    out[n] = o;
}

// ---------------- launcher (5 graph nodes) ----------------
extern "C" void kernel_launch(void* const* d_in, const int* in_sizes, int n_in,
                              void* d_out, int out_size) {
    const int*    ei        = (const int*)d_in[0];         // edge_index [2,E] int32
    const int*    et        = (const int*)d_in[1];         // edge_type  [E]   int32
    // d_in[2] edge_norm: unused by the reference forward
    const float*  basis1    = (const float*)d_in[3];       // [B,N,H]
    const float*  comp1     = (const float*)d_in[4];       // [R,B]
    const float4* root1     = (const float4*)d_in[5];      // [N,H]
    const float4* bias1     = (const float4*)d_in[6];      // [H]
    const float*  basis2    = (const float*)d_in[7];       // [B,H,C]
    const float*  comp2     = (const float*)d_in[8];       // [R,B]
    const float4* root2     = (const float4*)d_in[9];      // [H,C]
    const float4* bias2     = (const float4*)d_in[10];     // [C]
    float4* out = (float4*)d_out;

    (void)in_sizes; (void)n_in; (void)out_size;

    dim3 gw1((NH4 + 127) / 128, 2);
    k_w1   <<<gw1, 128>>>((const float4*)basis1, comp1);
    k_edge1<<<(EE + 255) / 256, 256>>>(ei, et);
    k_x_w2 <<<(NN + 255) / 256 + 1, 256>>>(root1, bias1, comp2, basis2);
    k_edge2<<<(EE + 255) / 256, 256>>>(ei, et);
    k_out  <<<(NN + 255) / 256, 256>>>(root2, bias2, out);
}